// round 6
// baseline (speedup 1.0000x reference)
#include <cuda_runtime.h>

#define NB      128     // persistent CTAs (< 148 SMs -> co-resident, barrier safe)
#define THREADS 256     // 8 warps, one per batch group, 2 per SMSP
#define BB      64      // batch
#define SS      2048    // seq len
#define HH      512     // hidden
#define VV      25      // vocab

// h double buffer (non-duplicated): [parity][k][batch-slot]
__device__ float g_h[2][HH * BB];
__device__ unsigned g_count;

__global__ void init_barrier_kernel() { g_count = 0u; }

// packed fp32x2 FMA (Blackwell): acc += x * y elementwise on 2 lanes
__device__ __forceinline__ void ffma2(float2& a, const float2 x, const float2 y) {
    asm("fma.rn.f32x2 %0, %1, %2, %0;"
        : "+l"(reinterpret_cast<unsigned long long&>(a))
        : "l"(reinterpret_cast<const unsigned long long&>(x)),
          "l"(reinterpret_cast<const unsigned long long&>(y)));
}

// fast, saturation-safe sigmoid / tanh
__device__ __forceinline__ float sigm(float x) {
    float e = __expf(-x);
    return __fdividef(1.f, 1.f + e);
}
__device__ __forceinline__ float tanha(float x) {
    return fmaf(2.f, sigm(2.f * x), -1.f);
}

// grid barrier: REDG release arrive + direct acquire-poll of one counter
__device__ __forceinline__ void grid_barrier(int tid, unsigned barno) {
    __syncthreads();
    if (tid == 0) {
        asm volatile("red.release.gpu.global.add.u32 [%0], 1;"
                     :: "l"(&g_count) : "memory");
        unsigned v;
        do {
            asm volatile("ld.acquire.gpu.global.u32 %0, [%1];"
                         : "=r"(v) : "l"(&g_count));
        } while (v < barno * (unsigned)NB);
    }
    __syncthreads();
}

// dynamic smem layout (floats)
#define WSP_FLOATS  (HH * 20)          // [k][20]: 16 rows (r=gate*4+j) + 4 pad (CONFLICT-FREE)
#define WXB_FLOATS  (16 * 32)          // [r][vocab padded 32], biases folded
#define SCR_FLOATS  (8 * 8 * 20)       // per-warp scratch [warp][batch8][16 rows + pad]
#define SMEM_BYTES  ((WSP_FLOATS + WXB_FLOATS + SCR_FLOATS + 3 * BB) * 4)

__global__ void __launch_bounds__(THREADS, 1) lstm_persistent_kernel(
    const int* __restrict__ tokens, const int* __restrict__ lengths,
    const float* __restrict__ W_ih, const float* __restrict__ W_hh,
    const float* __restrict__ b_ih, const float* __restrict__ b_hh,
    const float* __restrict__ fc_w, const float* __restrict__ fc_b,
    float* __restrict__ out)
{
    extern __shared__ char smem_raw[];
    float* wsp     = reinterpret_cast<float*>(smem_raw);
    float* wxb     = wsp + WSP_FLOATS;
    float* scratch = wxb + WXB_FLOATS;
    int*   slen    = reinterpret_cast<int*>(scratch + SCR_FLOATS);
    int*   sorder  = slen + BB;
    int*   lens    = sorder + BB;

    const int tid = threadIdx.x;
    const int c4  = blockIdx.x * 4;   // this CTA's 4 hidden dims

    // ---- W_hh chunk into smem: wsp[k*20 + r], r = gate*4 + j ----
    for (int idx = tid; idx < 16 * HH; idx += THREADS) {
        int r = idx >> 9, k = idx & (HH - 1);
        int R = (r >> 2) * HH + c4 + (r & 3);
        wsp[k * 20 + r] = W_hh[R * HH + k];
    }
    // ---- W_ih folded with biases ----
    for (int idx = tid; idx < 16 * VV; idx += THREADS) {
        int r = idx / VV, v = idx - r * VV;
        int R = (r >> 2) * HH + c4 + (r & 3);
        wxb[r * 32 + v] = W_ih[R * VV + v] + b_ih[R] + b_hh[R];
    }
    // ---- stable descending argsort of lengths ----
    if (tid < BB) lens[tid] = lengths[tid];
    __syncthreads();
    if (tid < BB) {
        int L = lens[tid], rk = 0;
        for (int b2 = 0; b2 < BB; b2++) {
            int L2 = lens[b2];
            rk += (L2 > L) || (L2 == L && b2 < tid);
        }
        sorder[rk] = tid;
        slen[rk]   = L;
    }
    // ---- zero this CTA's rows of h buffer 0 ----
    for (int idx = tid; idx < 4 * BB; idx += THREADS) {
        g_h[0][(c4 + (idx >> 6)) * BB + (idx & 63)] = 0.f;
    }
    __syncthreads();
    const int T = slen[0];

    // per-warp setup: warp g owns batch group g (8 batches), full k=512
    const int g = tid >> 5, lane = tid & 31;
    const int kq = lane >> 2, bp = lane & 3;      // 8-way k split, batch pair
    const int glen = slen[8 * g];                 // group max length
    float* sc = scratch + g * (8 * 20);           // this warp's scratch

    // per-lane activation cell: dim j, local batch bl
    const int aj = kq >> 1, ab2 = kq & 1;
    const int bl = 2 * bp + ab2;                  // 0..7
    const int sb = 8 * g + bl;                    // global batch slot
    const int alen = slen[sb];
    const int* tokrow = tokens + sorder[sb] * SS;
    float creg = 0.f;                             // this lane's cell state

    unsigned barno = 1;
    grid_barrier(tid, barno);

    for (int t = 0; t < T; t++) {
        const float* hr = g_h[t & 1];
        float*       hw = g_h[(t & 1) ^ 1];

        // early token fetch for this lane's cell
        int tok = 0;
        if (t < alen) tok = __ldg(tokrow + t);

        if (t < glen) {
            // ---- matmul: lane k = kq + 8*i, i<64; batches 8g+2bp, 8g+2bp+1 ----
            const float2* hp = reinterpret_cast<const float2*>(hr)
                               + (kq * 32 + 4 * g + bp);
            const float4* wp = reinterpret_cast<const float4*>(wsp) + kq * 5;
            float2 acc[8][2];   // acc[q][b2] = rows {2q,2q+1}, batch 8g+2bp+b2
#pragma unroll
            for (int q = 0; q < 8; q++) { acc[q][0] = make_float2(0.f, 0.f);
                                          acc[q][1] = make_float2(0.f, 0.f); }
            float2 hbuf[4];
#pragma unroll
            for (int j = 0; j < 4; j++) hbuf[j] = __ldcg(hp + j * 256);
            hp += 1024;
#pragma unroll 2
            for (int blk = 0; blk < 16; blk++) {
                float2 hcur[4];
#pragma unroll
                for (int j = 0; j < 4; j++) hcur[j] = hbuf[j];
                if (blk < 15) {
#pragma unroll
                    for (int j = 0; j < 4; j++) hbuf[j] = __ldcg(hp + j * 256);
                    hp += 1024;
                }
#pragma unroll
                for (int j = 0; j < 4; j++) {
                    float4 w0 = wp[0], w1 = wp[1], w2 = wp[2], w3 = wp[3];
                    wp += 40;
                    float2 ha = make_float2(hcur[j].x, hcur[j].x);
                    float2 hb = make_float2(hcur[j].y, hcur[j].y);
                    ffma2(acc[0][0], make_float2(w0.x, w0.y), ha);
                    ffma2(acc[0][1], make_float2(w0.x, w0.y), hb);
                    ffma2(acc[1][0], make_float2(w0.z, w0.w), ha);
                    ffma2(acc[1][1], make_float2(w0.z, w0.w), hb);
                    ffma2(acc[2][0], make_float2(w1.x, w1.y), ha);
                    ffma2(acc[2][1], make_float2(w1.x, w1.y), hb);
                    ffma2(acc[3][0], make_float2(w1.z, w1.w), ha);
                    ffma2(acc[3][1], make_float2(w1.z, w1.w), hb);
                    ffma2(acc[4][0], make_float2(w2.x, w2.y), ha);
                    ffma2(acc[4][1], make_float2(w2.x, w2.y), hb);
                    ffma2(acc[5][0], make_float2(w2.z, w2.w), ha);
                    ffma2(acc[5][1], make_float2(w2.z, w2.w), hb);
                    ffma2(acc[6][0], make_float2(w3.x, w3.y), ha);
                    ffma2(acc[6][1], make_float2(w3.x, w3.y), hb);
                    ffma2(acc[7][0], make_float2(w3.z, w3.w), ha);
                    ffma2(acc[7][1], make_float2(w3.z, w3.w), hb);
                }
            }
            // butterfly reduce over kq bits -> every lane holds full sums
#pragma unroll
            for (int m = 4; m <= 16; m <<= 1) {
#pragma unroll
                for (int q = 0; q < 8; q++) {
                    acc[q][0].x += __shfl_xor_sync(0xffffffffu, acc[q][0].x, m);
                    acc[q][0].y += __shfl_xor_sync(0xffffffffu, acc[q][0].y, m);
                    acc[q][1].x += __shfl_xor_sync(0xffffffffu, acc[q][1].x, m);
                    acc[q][1].y += __shfl_xor_sync(0xffffffffu, acc[q][1].y, m);
                }
            }
            // lanes 0-3 (kq==0) scatter to per-warp scratch: sc[bl][16 rows]
            if (lane < 4) {
#pragma unroll
                for (int b2 = 0; b2 < 2; b2++) {
                    float4* s4 = reinterpret_cast<float4*>(sc + (2 * bp + b2) * 20);
                    s4[0] = make_float4(acc[0][b2].x, acc[0][b2].y,
                                        acc[1][b2].x, acc[1][b2].y);
                    s4[1] = make_float4(acc[2][b2].x, acc[2][b2].y,
                                        acc[3][b2].x, acc[3][b2].y);
                    s4[2] = make_float4(acc[4][b2].x, acc[4][b2].y,
                                        acc[5][b2].x, acc[5][b2].y);
                    s4[3] = make_float4(acc[6][b2].x, acc[6][b2].y,
                                        acc[7][b2].x, acc[7][b2].y);
                }
            }
            __syncwarp();
        }

        // ---- activation: one LSTM cell per lane (dim c4+aj, batch sb) ----
        if (t <= glen) {
            float* hwp = hw + (c4 + aj) * BB + sb;
            if (t < alen) {   // implies t < glen (alen <= glen)
                const float* sr = sc + bl * 20;
                float gi = sr[aj]      + wxb[(aj)      * 32 + tok];
                float gf = sr[4 + aj]  + wxb[(4 + aj)  * 32 + tok];
                float gg = sr[8 + aj]  + wxb[(8 + aj)  * 32 + tok];
                float go = sr[12 + aj] + wxb[(12 + aj) * 32 + tok];
                float cn = sigm(gf) * creg + sigm(gi) * tanha(gg);
                creg = cn;
                __stcg(hwp, sigm(go) * tanha(cn));
            } else if (t == alen) {
                // first frozen step: mirror final h into the other parity buffer
                __stcg(hwp, __ldcg(hr + (c4 + aj) * BB + sb));
            }
        }

        barno++;
        grid_barrier(tid, barno);
    }

    // ---- final FC: out[s] = fc_w . h_final[:, s] + fc_b (sorted order) ----
    if (blockIdx.x == 0) {
        const float* hf = g_h[T & 1];
        int s = tid >> 2, q = tid & 3;
        float p = 0.f;
        for (int kk = 0; kk < 128; kk++) {
            int k = q * 128 + kk;
            p += __ldcg(&hf[k * BB + s]) * __ldg(&fc_w[k]);
        }
        p += __shfl_down_sync(0xffffffffu, p, 1);
        p += __shfl_down_sync(0xffffffffu, p, 2);
        if (q == 0) out[s] = p + __ldg(fc_b);
    }
}

extern "C" void kernel_launch(void* const* d_in, const int* in_sizes, int n_in,
                              void* d_out, int out_size) {
    const int*   tokens  = (const int*)d_in[0];
    const int*   lengths = (const int*)d_in[1];
    const float* W_ih    = (const float*)d_in[2];
    const float* W_hh    = (const float*)d_in[3];
    const float* b_ih    = (const float*)d_in[4];
    const float* b_hh    = (const float*)d_in[5];
    const float* fc_w    = (const float*)d_in[6];
    const float* fc_b    = (const float*)d_in[7];
    float* out = (float*)d_out;

    cudaFuncSetAttribute(lstm_persistent_kernel,
                         cudaFuncAttributeMaxDynamicSharedMemorySize, SMEM_BYTES);
    init_barrier_kernel<<<1, 1>>>();
    lstm_persistent_kernel<<<NB, THREADS, SMEM_BYTES>>>(
        tokens, lengths, W_ih, W_hh, b_ih, b_hh, fc_w, fc_b, out);
}

// round 7
// speedup vs baseline: 1.0194x; 1.0194x over previous
#include <cuda_runtime.h>

#define NB      128     // persistent CTAs = 32 dim-tiles x 4 batch-tiles
#define THREADS 512     // 16 warps, 4 per SMSP
#define BB      64      // batch
#define SS      2048    // seq len
#define HH      512     // hidden
#define VV      25      // vocab
#define DT      16      // dims per CTA
#define BT      16      // batches per CTA

// h double buffer: [parity][k][batch-slot]
__device__ float g_h[2][HH * BB];
__device__ unsigned g_count;

__global__ void init_barrier_kernel() { g_count = 0u; }

// packed fp32x2 FMA (Blackwell): acc += x * y elementwise on 2 lanes
__device__ __forceinline__ void ffma2(float2& a, const float2 x, const float2 y) {
    asm("fma.rn.f32x2 %0, %1, %2, %0;"
        : "+l"(reinterpret_cast<unsigned long long&>(a))
        : "l"(reinterpret_cast<const unsigned long long&>(x)),
          "l"(reinterpret_cast<const unsigned long long&>(y)));
}

// fast, saturation-safe sigmoid / tanh
__device__ __forceinline__ float sigm(float x) {
    float e = __expf(-x);
    return __fdividef(1.f, 1.f + e);
}
__device__ __forceinline__ float tanha(float x) {
    return fmaf(2.f, sigm(2.f * x), -1.f);
}

// grid barrier: REDG release arrive + direct acquire-poll of one counter
__device__ __forceinline__ void grid_barrier(int tid, unsigned barno) {
    __syncthreads();
    if (tid == 0) {
        asm volatile("red.release.gpu.global.add.u32 [%0], 1;"
                     :: "l"(&g_count) : "memory");
        unsigned v;
        do {
            asm volatile("ld.acquire.gpu.global.u32 %0, [%1];"
                         : "=r"(v) : "l"(&g_count));
        } while (v < barno * (unsigned)NB);
    }
    __syncthreads();
}

// dynamic smem layout (floats)
#define WSP_FLOATS  (HH * 68)          // [k][68]: 64 rows (pos = dp*8+g*2+jd) + 4 pad
#define WXB_FLOATS  (64 * 32)          // [r= g*16+d][vocab pad 32], biases folded
#define HST_FLOATS  (HH * 20)          // h stage [k][20]: 16 local batches + 4 pad
#define SMEM_BYTES  ((WSP_FLOATS + WXB_FLOATS + HST_FLOATS + 3 * BB) * 4)

__global__ void __launch_bounds__(THREADS, 1) lstm_persistent_kernel(
    const int* __restrict__ tokens, const int* __restrict__ lengths,
    const float* __restrict__ W_ih, const float* __restrict__ W_hh,
    const float* __restrict__ b_ih, const float* __restrict__ b_hh,
    const float* __restrict__ fc_w, const float* __restrict__ fc_b,
    float* __restrict__ out)
{
    extern __shared__ char smem_raw[];
    float* wsp  = reinterpret_cast<float*>(smem_raw);
    float* wxb  = wsp + WSP_FLOATS;
    float* hst  = wxb + WXB_FLOATS;
    int*   slen   = reinterpret_cast<int*>(hst + HST_FLOATS);
    int*   sorder = slen + BB;
    int*   lens   = sorder + BB;

    const int tid = threadIdx.x;
    const int dt = blockIdx.x >> 2;        // dim tile (16 dims)
    const int bt = blockIdx.x & 3;         // batch tile (16 batches)
    const int d0 = dt * DT, B0 = bt * BT;

    // ---- W_hh chunk: wsp[k*68 + pos], pos = (d>>1)*8 + g*2 + (d&1) ----
    for (int idx = tid; idx < 64 * HH; idx += THREADS) {
        int r = idx >> 9, k = idx & (HH - 1);     // r = g*16 + d, k fast (coalesced)
        int g = r >> 4, d = r & 15;
        int pos = (d >> 1) * 8 + g * 2 + (d & 1);
        wsp[k * 68 + pos] = W_hh[(g * HH + d0 + d) * HH + k];
    }
    // ---- W_ih folded with biases: wxb[(g*16+d)*32 + v] ----
    for (int idx = tid; idx < 64 * VV; idx += THREADS) {
        int r = idx / VV, v = idx - r * VV;
        int g = r >> 4, d = r & 15;
        int R = g * HH + d0 + d;
        wxb[r * 32 + v] = W_ih[R * VV + v] + b_ih[R] + b_hh[R];
    }
    // ---- stable descending argsort of lengths ----
    if (tid < BB) lens[tid] = lengths[tid];
    __syncthreads();
    if (tid < BB) {
        int L = lens[tid], rk = 0;
        for (int b2 = 0; b2 < BB; b2++) {
            int L2 = lens[b2];
            rk += (L2 > L) || (L2 == L && b2 < tid);
        }
        sorder[rk] = tid;
        slen[rk]   = L;
    }
    // ---- zero this CTA's cells in h buffer 0 ----
    if (tid < DT * BT) {
        int d = tid >> 4, b = tid & 15;
        g_h[0][(d0 + d) * BB + B0 + b] = 0.f;
    }
    __syncthreads();
    const int T      = slen[0];
    const int ctalen = slen[B0];           // CTA alive while t < ctalen

    // warp setup: warp = (dim pair dp, batch octet bh)
    const int w = tid >> 5, lane = tid & 31;
    const int dp = w >> 1, bh = w & 1;
    const int kq = lane >> 2, bp = lane & 3;       // 8-way k split, batch pair
    const int wlen = slen[B0 + 8 * bh];            // warp max length (sorted)

    // activation lanes: kq<4; cell = (dim jd of pair, batch 2bp+s)
    const bool act = (kq < 4);
    const int jd = kq & 1, s = (kq >> 1) & 1;
    const int lb = 8 * bh + 2 * bp + s;            // local batch 0..15
    const int sb = B0 + lb;                        // global batch slot
    const int alen  = slen[sb];
    const int dglob = d0 + 2 * dp + jd;
    const int* tokrow = tokens + sorder[sb] * SS;
    float creg = 0.f;

    unsigned barno = 1;
    grid_barrier(tid, barno);

    for (int t = 0; t < T; t++) {
        const float* hr = g_h[t & 1];
        float*       hw = g_h[(t & 1) ^ 1];

        // ---- stage h[512][16 local batches] into smem (32KB, L2 once/CTA) ----
        if (t < ctalen) {
            int kk = tid >> 3, j = tid & 7;                 // 8 float2 per thread
            const float2* src = reinterpret_cast<const float2*>(hr)
                                + (B0 >> 1) + j;
            float2 v[8];
#pragma unroll
            for (int p = 0; p < 8; p++) v[p] = __ldcg(src + (p * 64 + kk) * 32);
#pragma unroll
            for (int p = 0; p < 8; p++)
                *reinterpret_cast<float2*>(hst + (p * 64 + kk) * 20 + 2 * j) = v[p];
        }
        int tok = 0;
        if (act && t < alen) tok = __ldg(tokrow + t);
        __syncthreads();

        float2 acc[4][2];   // acc[g][s] = {dim0,dim1} sums, batch 8bh+2bp+s
        if (t < wlen) {
#pragma unroll
            for (int g = 0; g < 4; g++) { acc[g][0] = make_float2(0.f, 0.f);
                                          acc[g][1] = make_float2(0.f, 0.f); }
            const float2* hp = reinterpret_cast<const float2*>(hst)
                               + kq * 10 + 4 * bh + bp;     // k=kq, col pair 2bp
            const float4* wp = reinterpret_cast<const float4*>(wsp)
                               + kq * 17 + dp * 2;          // (kq*68 + dp*8)/4
#pragma unroll 16
            for (int i = 0; i < 64; i++) {                  // k = kq + 8*i
                float2 h2  = hp[i * 80];                    // 8 k * 10 float2
                float4 w01 = wp[i * 136];                   // 8 k * 17 float4
                float4 w23 = wp[i * 136 + 1];
                float2 ha = make_float2(h2.x, h2.x);
                float2 hb = make_float2(h2.y, h2.y);
                ffma2(acc[0][0], make_float2(w01.x, w01.y), ha);
                ffma2(acc[0][1], make_float2(w01.x, w01.y), hb);
                ffma2(acc[1][0], make_float2(w01.z, w01.w), ha);
                ffma2(acc[1][1], make_float2(w01.z, w01.w), hb);
                ffma2(acc[2][0], make_float2(w23.x, w23.y), ha);
                ffma2(acc[2][1], make_float2(w23.x, w23.y), hb);
                ffma2(acc[3][0], make_float2(w23.z, w23.w), ha);
                ffma2(acc[3][1], make_float2(w23.z, w23.w), hb);
            }
            // butterfly over kq bits (lane bits 2..4): all lanes get full sums
#pragma unroll
            for (int m = 4; m <= 16; m <<= 1) {
#pragma unroll
                for (int g = 0; g < 4; g++) {
                    acc[g][0].x += __shfl_xor_sync(0xffffffffu, acc[g][0].x, m);
                    acc[g][0].y += __shfl_xor_sync(0xffffffffu, acc[g][0].y, m);
                    acc[g][1].x += __shfl_xor_sync(0xffffffffu, acc[g][1].x, m);
                    acc[g][1].y += __shfl_xor_sync(0xffffffffu, acc[g][1].y, m);
                }
            }
        }

        // ---- activation: register-local, one cell per active lane ----
        if (act) {
            float* hwp = hw + dglob * BB + sb;
            if (t < alen) {   // alen <= wlen -> acc valid
                float2 a0 = s ? acc[0][1] : acc[0][0];
                float2 a1 = s ? acc[1][1] : acc[1][0];
                float2 a2 = s ? acc[2][1] : acc[2][0];
                float2 a3 = s ? acc[3][1] : acc[3][0];
                int dl = 2 * dp + jd;
                float gi = (jd ? a0.y : a0.x) + wxb[(0 * 16 + dl) * 32 + tok];
                float gf = (jd ? a1.y : a1.x) + wxb[(1 * 16 + dl) * 32 + tok];
                float gg = (jd ? a2.y : a2.x) + wxb[(2 * 16 + dl) * 32 + tok];
                float go = (jd ? a3.y : a3.x) + wxb[(3 * 16 + dl) * 32 + tok];
                float cn = sigm(gf) * creg + sigm(gi) * tanha(gg);
                creg = cn;
                __stcg(hwp, sigm(go) * tanha(cn));
            } else if (t == alen) {
                // first frozen step: mirror final h into the other parity buffer
                __stcg(hwp, __ldcg(hr + dglob * BB + sb));
            }
        }

        barno++;
        grid_barrier(tid, barno);
    }

    // ---- final FC: out[s] = fc_w . h_final[:, s] + fc_b (sorted order) ----
    if (blockIdx.x == 0 && tid < 256) {
        const float* hf = g_h[T & 1];
        int so = tid >> 2, q = tid & 3;
        float p = 0.f;
        for (int kk = 0; kk < 128; kk++) {
            int k = q * 128 + kk;
            p += __ldcg(&hf[k * BB + so]) * __ldg(&fc_w[k]);
        }
        p += __shfl_down_sync(0xffffffffu, p, 1);
        p += __shfl_down_sync(0xffffffffu, p, 2);
        if (q == 0) out[so] = p + __ldg(fc_b);
    }
}

extern "C" void kernel_launch(void* const* d_in, const int* in_sizes, int n_in,
                              void* d_out, int out_size) {
    const int*   tokens  = (const int*)d_in[0];
    const int*   lengths = (const int*)d_in[1];
    const float* W_ih    = (const float*)d_in[2];
    const float* W_hh    = (const float*)d_in[3];
    const float* b_ih    = (const float*)d_in[4];
    const float* b_hh    = (const float*)d_in[5];
    const float* fc_w    = (const float*)d_in[6];
    const float* fc_b    = (const float*)d_in[7];
    float* out = (float*)d_out;

    cudaFuncSetAttribute(lstm_persistent_kernel,
                         cudaFuncAttributeMaxDynamicSharedMemorySize, SMEM_BYTES);
    init_barrier_kernel<<<1, 1>>>();
    lstm_persistent_kernel<<<NB, THREADS, SMEM_BYTES>>>(
        tokens, lengths, W_ih, W_hh, b_ih, b_hh, fc_w, fc_b, out);
}

// round 9
// speedup vs baseline: 1.0251x; 1.0056x over previous
#include <cuda_runtime.h>

#define NB      128     // 32 dim-tiles x 4 batch-tiles, persistent
#define THREADS 512     // 16 warps = rg(4) x kh(4), 4 per SMSP
#define BB      64
#define SS      2048
#define HH      512
#define VV      25
#define DT      16      // dims per CTA
#define BT      16      // batches per CTA

__device__ float g_h[2][HH * BB];    // [parity][k*64 + batch-slot]
__device__ unsigned g_count;

__global__ void init_barrier_kernel() { g_count = 0u; }

__device__ __forceinline__ void ffma2(float2& a, const float2 x, const float2 y) {
    asm("fma.rn.f32x2 %0, %1, %2, %0;"
        : "+l"(reinterpret_cast<unsigned long long&>(a))
        : "l"(reinterpret_cast<const unsigned long long&>(x)),
          "l"(reinterpret_cast<const unsigned long long&>(y)));
}

__device__ __forceinline__ float sigm(float x) {
    float e = __expf(-x);
    return __fdividef(1.f, 1.f + e);
}
__device__ __forceinline__ float tanha(float x) {
    return fmaf(2.f, sigm(2.f * x), -1.f);
}

__device__ __forceinline__ void grid_barrier(int tid, unsigned barno) {
    __syncthreads();
    if (tid == 0) {
        asm volatile("red.release.gpu.global.add.u32 [%0], 1;"
                     :: "l"(&g_count) : "memory");
        unsigned v;
        do {
            asm volatile("ld.acquire.gpu.global.u32 %0, [%1];"
                         : "=r"(v) : "l"(&g_count));
        } while (v < barno * (unsigned)NB);
    }
    __syncthreads();
}

// smem (floats): W [k][68]: 64 rows (rg*16 + gate*4 + dj) + 4 pad  -> conflict-free
#define WSP_FLOATS  (HH * 68)              // 139264 B
#define WXB_FLOATS  (64 * 32)              // token proj + biases
#define GRD_FLOATS  (16 * 16 * 20)         // [(rg*4+kh)*16 + b][16 rows + 4 pad] (16B-aligned rows)
#define SMEM_BYTES  ((WSP_FLOATS + WXB_FLOATS + GRD_FLOATS + 3 * BB) * 4)

__global__ void __launch_bounds__(THREADS, 1) lstm_persistent_kernel(
    const int* __restrict__ tokens, const int* __restrict__ lengths,
    const float* __restrict__ W_ih, const float* __restrict__ W_hh,
    const float* __restrict__ b_ih, const float* __restrict__ b_hh,
    const float* __restrict__ fc_w, const float* __restrict__ fc_b,
    float* __restrict__ out)
{
    extern __shared__ char smem_raw[];
    float* wsp  = reinterpret_cast<float*>(smem_raw);
    float* wxb  = wsp + WSP_FLOATS;
    float* gred = wxb + WXB_FLOATS;
    int*   slen   = reinterpret_cast<int*>(gred + GRD_FLOATS);
    int*   sorder = slen + BB;
    int*   lens   = sorder + BB;

    const int tid = threadIdx.x;
    const int dt = blockIdx.x >> 2, bt = blockIdx.x & 3;
    const int d0 = dt * DT, B0 = bt * BT;

    // ---- W_hh: wsp[k*68 + rg*16 + gate*4 + dj], gmem read k-fast (coalesced) ----
    for (int idx = tid; idx < 64 * HH; idx += THREADS) {
        int r = idx >> 9, k = idx & (HH - 1);      // r = rg*16 + gate*4 + dj
        int rg = r >> 4, gate = (r >> 2) & 3, dj = r & 3;
        wsp[k * 68 + r] = W_hh[(gate * HH + d0 + rg * 4 + dj) * HH + k];
    }
    // ---- W_ih + biases: wxb[r*32 + v] ----
    for (int idx = tid; idx < 64 * VV; idx += THREADS) {
        int r = idx / VV, v = idx - r * VV;
        int rg = r >> 4, gate = (r >> 2) & 3, dj = r & 3;
        int R = gate * HH + d0 + rg * 4 + dj;
        wxb[r * 32 + v] = W_ih[R * VV + v] + b_ih[R] + b_hh[R];
    }
    // ---- stable descending argsort ----
    if (tid < BB) lens[tid] = lengths[tid];
    __syncthreads();
    if (tid < BB) {
        int L = lens[tid], rk = 0;
        for (int b2 = 0; b2 < BB; b2++) {
            int L2 = lens[b2];
            rk += (L2 > L) || (L2 == L && b2 < tid);
        }
        sorder[rk] = tid;
        slen[rk]   = L;
    }
    // ---- zero this CTA's h(0) cells ----
    if (tid < DT * BT) {
        g_h[0][(d0 + (tid >> 4)) * BB + B0 + (tid & 15)] = 0.f;
    }
    __syncthreads();
    const int T      = slen[0];
    const int ctalen = slen[B0];          // CTA alive while t < ctalen (sorted desc)

    // warp setup: w = rg*4 + kh
    const int w = tid >> 5, lane = tid & 31;
    const int rg = w >> 2, kh = w & 3;              // row quad (4 dims), k quarter
    const int kq = lane >> 2, bp = lane & 3;        // 8-way k split, batch quad
    const int kbase = kh * 128 + kq;                // lane k: kbase + 8*i, i<16

    // activation mapping (kh==0 warps): lane -> (dim-pair dj0/dj0+2, batch b)
    const int ab = lane & 15, adj = lane >> 4;      // batch 0..15, dj0 in {0,1}
    const int sb = B0 + ab;
    const int alen = slen[sb];
    const int dG0 = d0 + rg * 4 + adj;              // dims dG0, dG0+2
    const int* tokrow = tokens + sorder[sb] * SS;
    float creg0 = 0.f, creg1 = 0.f;

    unsigned barno = 1;
    grid_barrier(tid, barno);

    for (int t = 0; t < T; t++) {
        const float* hr = g_h[t & 1];
        float*       hw = g_h[(t & 1) ^ 1];

        int tok = 0;
        if (kh == 0 && t < alen) tok = __ldg(tokrow + t);

        if (t < ctalen) {
            // ---- matmul: 16 rows (rg) x 16 batches x 128 k (kh) per warp ----
            const float4* hp = reinterpret_cast<const float4*>(hr + kbase * BB + B0) + bp;
            const float4* wp = reinterpret_cast<const float4*>(wsp + kbase * 68 + rg * 16);
            float2 acc[4][2][4];   // [gate][dim-pair][batch]
#pragma unroll
            for (int gg = 0; gg < 4; gg++)
#pragma unroll
                for (int dp2 = 0; dp2 < 2; dp2++)
#pragma unroll
                    for (int b = 0; b < 4; b++) acc[gg][dp2][b] = make_float2(0.f, 0.f);

            // software pipeline depth 4 on h (stride per k-step-of-8: 8*64 floats = 128 f4)
            float4 hbuf[4];
#pragma unroll
            for (int j = 0; j < 4; j++) hbuf[j] = __ldcg(hp + j * 128);
#pragma unroll
            for (int blk = 0; blk < 4; blk++) {
                float4 hcur[4];
#pragma unroll
                for (int j = 0; j < 4; j++) hcur[j] = hbuf[j];
                if (blk < 3) {
#pragma unroll
                    for (int j = 0; j < 4; j++)
                        hbuf[j] = __ldcg(hp + ((blk + 1) * 4 + j) * 128);
                }
#pragma unroll
                for (int j = 0; j < 4; j++) {
                    const float4* wk = wp + (blk * 4 + j) * (8 * 17);  // 8 k * 68 floats
                    float4 w0 = wk[0], w1 = wk[1], w2 = wk[2], w3 = wk[3];
                    float4 h4 = hcur[j];
#pragma unroll
                    for (int b = 0; b < 4; b++) {
                        float hv = (b == 0) ? h4.x : (b == 1) ? h4.y
                                 : (b == 2) ? h4.z : h4.w;
                        float2 hb = make_float2(hv, hv);
                        ffma2(acc[0][0][b], make_float2(w0.x, w0.y), hb);
                        ffma2(acc[0][1][b], make_float2(w0.z, w0.w), hb);
                        ffma2(acc[1][0][b], make_float2(w1.x, w1.y), hb);
                        ffma2(acc[1][1][b], make_float2(w1.z, w1.w), hb);
                        ffma2(acc[2][0][b], make_float2(w2.x, w2.y), hb);
                        ffma2(acc[2][1][b], make_float2(w2.z, w2.w), hb);
                        ffma2(acc[3][0][b], make_float2(w3.x, w3.y), hb);
                        ffma2(acc[3][1][b], make_float2(w3.z, w3.w), hb);
                    }
                }
            }
            // butterfly over kq (lane bits 2..4): all lanes get warp-k-range sums
#pragma unroll
            for (int m = 4; m <= 16; m <<= 1) {
#pragma unroll
                for (int gg = 0; gg < 4; gg++)
#pragma unroll
                    for (int dp2 = 0; dp2 < 2; dp2++)
#pragma unroll
                        for (int b = 0; b < 4; b++) {
                            acc[gg][dp2][b].x += __shfl_xor_sync(0xffffffffu, acc[gg][dp2][b].x, m);
                            acc[gg][dp2][b].y += __shfl_xor_sync(0xffffffffu, acc[gg][dp2][b].y, m);
                        }
            }
            // lanes kq==0 (lane = bp) store 4 batches x 16 rows to gred (stride 20: 80B, aligned)
            if (lane < 4) {
                float* gbase = gred + ((rg * 4 + kh) * 16) * 20;
#pragma unroll
                for (int b = 0; b < 4; b++) {
                    float4* s4 = reinterpret_cast<float4*>(gbase + (4 * bp + b) * 20);
#pragma unroll
                    for (int gg = 0; gg < 4; gg++)
                        s4[gg] = make_float4(acc[gg][0][b].x, acc[gg][0][b].y,
                                             acc[gg][1][b].x, acc[gg][1][b].y);
                }
            }
            // rg-quad sync: all 4 kh warps' partials visible
            asm volatile("bar.sync %0, 128;" :: "r"(rg + 1) : "memory");
        }

        // ---- activation: kh==0 warps, 2 cells/lane (dims adj, adj+2; batch sb) ----
        if (kh == 0 && t <= ctalen) {
            if (t < alen) {   // alen <= ctalen -> gred valid
                const float* g0 = gred + ((rg * 4 + 0) * 16 + ab) * 20;
                const float* g1 = g0 + 16 * 20;
                const float* g2 = g1 + 16 * 20;
                const float* g3 = g2 + 16 * 20;
#pragma unroll
                for (int cell = 0; cell < 2; cell++) {
                    int dj = adj + 2 * cell;
                    float gi = g0[0 * 4 + dj] + g1[0 * 4 + dj] + g2[0 * 4 + dj] + g3[0 * 4 + dj]
                             + wxb[(rg * 16 + 0 * 4 + dj) * 32 + tok];
                    float gf = g0[1 * 4 + dj] + g1[1 * 4 + dj] + g2[1 * 4 + dj] + g3[1 * 4 + dj]
                             + wxb[(rg * 16 + 1 * 4 + dj) * 32 + tok];
                    float gg = g0[2 * 4 + dj] + g1[2 * 4 + dj] + g2[2 * 4 + dj] + g3[2 * 4 + dj]
                             + wxb[(rg * 16 + 2 * 4 + dj) * 32 + tok];
                    float go = g0[3 * 4 + dj] + g1[3 * 4 + dj] + g2[3 * 4 + dj] + g3[3 * 4 + dj]
                             + wxb[(rg * 16 + 3 * 4 + dj) * 32 + tok];
                    float cold = cell ? creg1 : creg0;
                    float cn = sigm(gf) * cold + sigm(gi) * tanha(gg);
                    if (cell) creg1 = cn; else creg0 = cn;
                    __stcg(hw + (dG0 + 2 * cell) * BB + sb, sigm(go) * tanha(cn));
                }
            } else if (t == alen) {
                __stcg(hw + dG0 * BB + sb,       __ldcg(hr + dG0 * BB + sb));
                __stcg(hw + (dG0 + 2) * BB + sb, __ldcg(hr + (dG0 + 2) * BB + sb));
            }
        }

        barno++;
        grid_barrier(tid, barno);
    }

    // ---- final FC: out[s] = fc_w . h_final[:, s] + fc_b (sorted order) ----
    if (blockIdx.x == 0 && tid < 256) {
        const float* hf = g_h[T & 1];
        int so = tid >> 2, q = tid & 3;
        float p = 0.f;
        for (int kk = 0; kk < 128; kk++) {
            int k = q * 128 + kk;
            p += __ldcg(&hf[k * BB + so]) * __ldg(&fc_w[k]);
        }
        p += __shfl_down_sync(0xffffffffu, p, 1);
        p += __shfl_down_sync(0xffffffffu, p, 2);
        if (q == 0) out[so] = p + __ldg(fc_b);
    }
}

extern "C" void kernel_launch(void* const* d_in, const int* in_sizes, int n_in,
                              void* d_out, int out_size) {
    const int*   tokens  = (const int*)d_in[0];
    const int*   lengths = (const int*)d_in[1];
    const float* W_ih    = (const float*)d_in[2];
    const float* W_hh    = (const float*)d_in[3];
    const float* b_ih    = (const float*)d_in[4];
    const float* b_hh    = (const float*)d_in[5];
    const float* fc_w    = (const float*)d_in[6];
    const float* fc_b    = (const float*)d_in[7];
    float* out = (float*)d_out;

    cudaFuncSetAttribute(lstm_persistent_kernel,
                         cudaFuncAttributeMaxDynamicSharedMemorySize, SMEM_BYTES);
    init_barrier_kernel<<<1, 1>>>();
    lstm_persistent_kernel<<<NB, THREADS, SMEM_BYTES>>>(
        tokens, lengths, W_ih, W_hh, b_ih, b_hh, fc_w, fc_b, out);
}

// round 11
// speedup vs baseline: 1.4238x; 1.3890x over previous
#include <cuda_runtime.h>

#define NQ      4       // independent batch quadrants
#define NBQ     32      // CTAs per quadrant (16 dims each)
#define THREADS 512     // 16 warps = rg(4) x kh(4)
#define BB      64
#define SS      2048
#define HH      512
#define VV      25
#define DT      16      // dims per CTA
#define BT      16      // batches per quadrant/CTA

// per-quadrant h double buffers, dense rows: [q][parity][k*16 + local batch]
__device__ __align__(16) float g_hq[NQ][2][HH * BT];
__device__ unsigned g_cnt[NQ * 32];    // counters 128B apart

__global__ void init_barrier_kernel() {
    for (int q = 0; q < NQ; q++) g_cnt[q * 32] = 0u;
}

__device__ __forceinline__ void ffma2(float2& a, const float2 x, const float2 y) {
    asm("fma.rn.f32x2 %0, %1, %2, %0;"
        : "+l"(reinterpret_cast<unsigned long long&>(a))
        : "l"(reinterpret_cast<const unsigned long long&>(x)),
          "l"(reinterpret_cast<const unsigned long long&>(y)));
}

__device__ __forceinline__ float sigm(float x) {
    float e = __expf(-x);
    return __fdividef(1.f, 1.f + e);
}
__device__ __forceinline__ float tanha(float x) {
    return fmaf(2.f, sigm(2.f * x), -1.f);
}

// quadrant barrier: REDG release arrive + acquire-poll of quadrant counter
__device__ __forceinline__ void quad_barrier(int tid, unsigned barno, unsigned* cnt) {
    __syncthreads();
    if (tid == 0) {
        asm volatile("red.release.gpu.global.add.u32 [%0], 1;"
                     :: "l"(cnt) : "memory");
        unsigned v;
        do {
            asm volatile("ld.acquire.gpu.global.u32 %0, [%1];"
                         : "=r"(v) : "l"(cnt));
        } while (v < barno * (unsigned)NBQ);
    }
    __syncthreads();
}

// smem (floats)
#define WSP_FLOATS  (HH * 68)          // [k][68]: 64 rows (rg*16+gate*4+dj) + 4 pad
#define WXB_FLOATS  (64 * 32)
#define GRD_FLOATS  (16 * 16 * 20)     // [(rg*4+kh)*16 + b][16 rows + 4 pad]
#define SMEM_BYTES  ((WSP_FLOATS + WXB_FLOATS + GRD_FLOATS + 3 * BB) * 4)

__global__ void __launch_bounds__(THREADS, 1) lstm_persistent_kernel(
    const int* __restrict__ tokens, const int* __restrict__ lengths,
    const float* __restrict__ W_ih, const float* __restrict__ W_hh,
    const float* __restrict__ b_ih, const float* __restrict__ b_hh,
    const float* __restrict__ fc_w, const float* __restrict__ fc_b,
    float* __restrict__ out)
{
    extern __shared__ char smem_raw[];
    float* wsp  = reinterpret_cast<float*>(smem_raw);
    float* wxb  = wsp + WSP_FLOATS;
    float* gred = wxb + WXB_FLOATS;
    int*   slen   = reinterpret_cast<int*>(gred + GRD_FLOATS);
    int*   sorder = slen + BB;
    int*   lens   = sorder + BB;

    const int tid = threadIdx.x;
    const int dt = blockIdx.x >> 2, bt = blockIdx.x & 3;   // dim tile, quadrant
    const int d0 = dt * DT, B0 = bt * BT;
    unsigned* cnt = &g_cnt[bt * 32];
    float* hq0 = g_hq[bt][0];
    float* hq1 = g_hq[bt][1];

    // ---- W_hh: wsp[k*68 + rg*16 + gate*4 + dj] ----
    for (int idx = tid; idx < 64 * HH; idx += THREADS) {
        int r = idx >> 9, k = idx & (HH - 1);
        int rg = r >> 4, gate = (r >> 2) & 3, dj = r & 3;
        wsp[k * 68 + r] = W_hh[(gate * HH + d0 + rg * 4 + dj) * HH + k];
    }
    // ---- W_ih + biases ----
    for (int idx = tid; idx < 64 * VV; idx += THREADS) {
        int r = idx / VV, v = idx - r * VV;
        int rg = r >> 4, gate = (r >> 2) & 3, dj = r & 3;
        int R = gate * HH + d0 + rg * 4 + dj;
        wxb[r * 32 + v] = W_ih[R * VV + v] + b_ih[R] + b_hh[R];
    }
    // ---- stable descending argsort ----
    if (tid < BB) lens[tid] = lengths[tid];
    __syncthreads();
    if (tid < BB) {
        int L = lens[tid], rk = 0;
        for (int b2 = 0; b2 < BB; b2++) {
            int L2 = lens[b2];
            rk += (L2 > L) || (L2 == L && b2 < tid);
        }
        sorder[rk] = tid;
        slen[rk]   = L;
    }
    // ---- zero this CTA's cells in quadrant h buffer 0 ----
    if (tid < DT * BT) {
        hq0[(d0 + (tid >> 4)) * BT + (tid & 15)] = 0.f;
    }
    __syncthreads();
    const int ctalen = slen[B0];          // quadrant length (max of its 16, sorted)

    // warp setup
    const int w = tid >> 5, lane = tid & 31;
    const int rg = w >> 2, kh = w & 3;
    const int kq = lane >> 2, bp = lane & 3;
    const int b2 = (lane >> 2) & 1, b3 = (lane >> 3) & 1, b4 = (lane >> 4) & 1;
    const int kbase = kh * 128 + kq;

    // activation warp: kh == rg  -> one per SMSP
    const bool actw = (kh == rg);
    const int ab = lane & 15, adj = lane >> 4;
    const int sb = B0 + ab;
    const int alen = slen[sb];
    const int dG0 = d0 + rg * 4 + adj;
    const int* tokrow = tokens + sorder[sb] * SS;
    float creg0 = 0.f, creg1 = 0.f;

    unsigned barno = 1;
    quad_barrier(tid, barno, cnt);

    for (int t = 0; t < ctalen; t++) {
        const float* hr = (t & 1) ? hq1 : hq0;
        float*       hw = (t & 1) ? hq0 : hq1;

        int tok = 0;
        if (actw && t < alen) tok = __ldg(tokrow + t);

        // ---- matmul: warp = 16 rows x 16 batches x 128 k; dense h rows ----
        const float4* hp = reinterpret_cast<const float4*>(hr) + kbase * 4 + bp;
        const float4* wp = reinterpret_cast<const float4*>(wsp) + kbase * 17 + rg * 4;
        float2 acc[4][2][4];   // [gate][dim-pair][batch]
#pragma unroll
        for (int gg = 0; gg < 4; gg++)
#pragma unroll
            for (int dp2 = 0; dp2 < 2; dp2++)
#pragma unroll
                for (int b = 0; b < 4; b++) acc[gg][dp2][b] = make_float2(0.f, 0.f);

        float4 hbuf[4];
#pragma unroll
        for (int j = 0; j < 4; j++) hbuf[j] = __ldcg(hp + j * 32);   // 8k = 32 f4
#pragma unroll
        for (int blk = 0; blk < 4; blk++) {
            float4 hcur[4];
#pragma unroll
            for (int j = 0; j < 4; j++) hcur[j] = hbuf[j];
            if (blk < 3) {
#pragma unroll
                for (int j = 0; j < 4; j++)
                    hbuf[j] = __ldcg(hp + ((blk + 1) * 4 + j) * 32);
            }
#pragma unroll
            for (int j = 0; j < 4; j++) {
                const float4* wk = wp + (blk * 4 + j) * 136;   // 8 k * 17 f4
                float4 w0 = wk[0], w1 = wk[1], w2 = wk[2], w3 = wk[3];
                float4 h4 = hcur[j];
#pragma unroll
                for (int b = 0; b < 4; b++) {
                    float hv = (b == 0) ? h4.x : (b == 1) ? h4.y
                             : (b == 2) ? h4.z : h4.w;
                    float2 hb = make_float2(hv, hv);
                    ffma2(acc[0][0][b], make_float2(w0.x, w0.y), hb);
                    ffma2(acc[0][1][b], make_float2(w0.z, w0.w), hb);
                    ffma2(acc[1][0][b], make_float2(w1.x, w1.y), hb);
                    ffma2(acc[1][1][b], make_float2(w1.z, w1.w), hb);
                    ffma2(acc[2][0][b], make_float2(w2.x, w2.y), hb);
                    ffma2(acc[2][1][b], make_float2(w2.z, w2.w), hb);
                    ffma2(acc[3][0][b], make_float2(w3.x, w3.y), hb);
                    ffma2(acc[3][1][b], make_float2(w3.z, w3.w), hb);
                }
            }
        }

        // ---- reduce-scatter over kq bits (in-place; 56 shfl/lane) ----
        // R1 (xor 4, bit b2): keep gate pair {2*b2, 2*b2+1}  -> acc[gp][dp2][b]
#pragma unroll
        for (int gp = 0; gp < 2; gp++)
#pragma unroll
            for (int dp2 = 0; dp2 < 2; dp2++)
#pragma unroll
                for (int b = 0; b < 4; b++) {
                    float2 X = acc[gp][dp2][b], Y = acc[2 + gp][dp2][b];
                    float gx = b2 ? X.x : Y.x, gy = b2 ? X.y : Y.y;
                    float rx = __shfl_xor_sync(0xffffffffu, gx, 4);
                    float ry = __shfl_xor_sync(0xffffffffu, gy, 4);
                    float kx = b2 ? Y.x : X.x, ky = b2 ? Y.y : X.y;
                    acc[gp][dp2][b] = make_float2(kx + rx, ky + ry);
                }
        // R2 (xor 8, bit b3): keep dim-pair b3 -> acc[gp][0][b]
#pragma unroll
        for (int gp = 0; gp < 2; gp++)
#pragma unroll
            for (int b = 0; b < 4; b++) {
                float2 X = acc[gp][0][b], Y = acc[gp][1][b];
                float gx = b3 ? X.x : Y.x, gy = b3 ? X.y : Y.y;
                float rx = __shfl_xor_sync(0xffffffffu, gx, 8);
                float ry = __shfl_xor_sync(0xffffffffu, gy, 8);
                float kx = b3 ? Y.x : X.x, ky = b3 ? Y.y : X.y;
                acc[gp][0][b] = make_float2(kx + rx, ky + ry);
            }
        // R3 (xor 16, bit b4): keep batch pair {2*b4, 2*b4+1} -> acc[gp][0][bq]
#pragma unroll
        for (int gp = 0; gp < 2; gp++)
#pragma unroll
            for (int bq = 0; bq < 2; bq++) {
                float2 X = acc[gp][0][bq], Y = acc[gp][0][2 + bq];
                float gx = b4 ? X.x : Y.x, gy = b4 ? X.y : Y.y;
                float rx = __shfl_xor_sync(0xffffffffu, gx, 16);
                float ry = __shfl_xor_sync(0xffffffffu, gy, 16);
                float kx = b4 ? Y.x : X.x, ky = b4 ? Y.y : X.y;
                acc[gp][0][bq] = make_float2(kx + rx, ky + ry);
            }
        // every lane stores its 4 float2: gate = 2*b2+gp, dims dj = 2*b3+{0,1},
        // batch = 4*bp + 2*b4 + bq.  In-row offset = gate*4 + 2*b3 = 8*b2 + 4*gp + 2*b3
        {
            float* gb = gred + ((rg * 4 + kh) * 16) * 20 + (8 * b2 + 2 * b3);
#pragma unroll
            for (int gp = 0; gp < 2; gp++)
#pragma unroll
                for (int bq = 0; bq < 2; bq++) {
                    int batch = 4 * bp + 2 * b4 + bq;
                    *reinterpret_cast<float2*>(
                        gb + batch * 20 + gp * 4) = acc[gp][0][bq];
                }
        }
        // rg-quad sync (4 warps, 128 threads)
        asm volatile("bar.sync %0, 128;" :: "r"(rg + 1) : "memory");

        // ---- activation: warp kh==rg, 2 cells/lane ----
        if (actw) {
            if (t < alen) {
                const float* g0 = gred + ((rg * 4 + 0) * 16 + ab) * 20;
                const float* g1 = g0 + 16 * 20;
                const float* g2 = g1 + 16 * 20;
                const float* g3 = g2 + 16 * 20;
#pragma unroll
                for (int cell = 0; cell < 2; cell++) {
                    int dj = adj + 2 * cell;
                    float gi = g0[0 * 4 + dj] + g1[0 * 4 + dj] + g2[0 * 4 + dj] + g3[0 * 4 + dj]
                             + wxb[(rg * 16 + 0 * 4 + dj) * 32 + tok];
                    float gf = g0[1 * 4 + dj] + g1[1 * 4 + dj] + g2[1 * 4 + dj] + g3[1 * 4 + dj]
                             + wxb[(rg * 16 + 1 * 4 + dj) * 32 + tok];
                    float gg = g0[2 * 4 + dj] + g1[2 * 4 + dj] + g2[2 * 4 + dj] + g3[2 * 4 + dj]
                             + wxb[(rg * 16 + 2 * 4 + dj) * 32 + tok];
                    float go = g0[3 * 4 + dj] + g1[3 * 4 + dj] + g2[3 * 4 + dj] + g3[3 * 4 + dj]
                             + wxb[(rg * 16 + 3 * 4 + dj) * 32 + tok];
                    float cold = cell ? creg1 : creg0;
                    float cn = sigm(gf) * cold + sigm(gi) * tanha(gg);
                    if (cell) creg1 = cn; else creg0 = cn;
                    __stcg(hw + (dG0 + 2 * cell) * BT + ab, sigm(go) * tanha(cn));
                }
            } else if (t == alen) {
                __stcg(hw + dG0 * BT + ab,       __ldcg(hr + dG0 * BT + ab));
                __stcg(hw + (dG0 + 2) * BT + ab, __ldcg(hr + (dG0 + 2) * BT + ab));
            }
        }

        barno++;
        quad_barrier(tid, barno, cnt);
    }

    // ---- final FC for this quadrant (dt==0 CTA): warp j -> batch B0+j ----
    if (dt == 0) {
        const float* hf = (ctalen & 1) ? hq1 : hq0;
        int j = tid >> 5, l = tid & 31;
        float p = 0.f;
#pragma unroll
        for (int i = 0; i < 16; i++) {
            int k = l + 32 * i;
            p += __ldcg(hf + k * BT + j) * __ldg(fc_w + k);
        }
#pragma unroll
        for (int m = 16; m >= 1; m >>= 1)
            p += __shfl_xor_sync(0xffffffffu, p, m);
        if (l == 0) out[B0 + j] = p + __ldg(fc_b);
    }
}

extern "C" void kernel_launch(void* const* d_in, const int* in_sizes, int n_in,
                              void* d_out, int out_size) {
    const int*   tokens  = (const int*)d_in[0];
    const int*   lengths = (const int*)d_in[1];
    const float* W_ih    = (const float*)d_in[2];
    const float* W_hh    = (const float*)d_in[3];
    const float* b_ih    = (const float*)d_in[4];
    const float* b_hh    = (const float*)d_in[5];
    const float* fc_w    = (const float*)d_in[6];
    const float* fc_b    = (const float*)d_in[7];
    float* out = (float*)d_out;

    cudaFuncSetAttribute(lstm_persistent_kernel,
                         cudaFuncAttributeMaxDynamicSharedMemorySize, SMEM_BYTES);
    init_barrier_kernel<<<1, 1>>>();
    lstm_persistent_kernel<<<NQ * NBQ, THREADS, SMEM_BYTES>>>(
        tokens, lengths, W_ih, W_hh, b_ih, b_hh, fc_w, fc_b, out);
}